// round 5
// baseline (speedup 1.0000x reference)
#include <cuda_runtime.h>
#include <math.h>

// ---------------- output layout (concatenated tuple, fp32) ----------------
#define ANCHOR_ELEMS (3*127*127)
#define N_ANCHOR     (64*ANCHOR_ELEMS)
#define N_CX         (64*17*17)
#define N_MU         (64*32*14*14)
#define OFF_ANCHOR   0
#define OFF_CXP      (OFF_ANCHOR + N_ANCHOR)
#define OFF_CXN      (OFF_CXP + N_CX)
#define OFF_RECON    (OFF_CXN + N_CX)
#define OFF_MU       (OFF_RECON + N_ANCHOR)
#define OFF_LV       (OFF_MU + N_MU)

// ---------------- scratch ----------------
__device__ float g_buf1[128*32*126*126];  // conv1 out
__device__ float g_buf2[128*64*62*62];    // conv2 out
__device__ float g_pnf [128*64*30*30];    // conv3 out (pos+neg)
__device__ float g_h   [65*64*14*14];     // crop conv3 out (n=64 is anchor)
__device__ float g_z   [64*32*14*14];
__device__ float g_d0  [64*64*14*14];
__device__ float g_d1  [64*32*30*30];
__device__ float g_d2  [64*16*62*62];

static inline int div_up(int a, int b) { return (a + b - 1) / b; }

// ---------------- f32x2 packed-FMA helpers ----------------
__device__ __forceinline__ unsigned long long pk_dup(float v) {
    unsigned long long r; unsigned int u = __float_as_uint(v);
    asm("mov.b64 %0, {%1, %1};" : "=l"(r) : "r"(u));
    return r;
}
__device__ __forceinline__ unsigned long long pk2(float a, float b) {
    unsigned long long r;
    asm("mov.b64 %0, {%1, %2};" : "=l"(r) : "r"(__float_as_uint(a)), "r"(__float_as_uint(b)));
    return r;
}
__device__ __forceinline__ void fma2(unsigned long long& acc, unsigned long long a, unsigned long long b) {
    asm("fma.rn.f32x2 %0, %1, %2, %0;" : "+l"(acc) : "l"(a), "l"(b));
}
__device__ __forceinline__ float2 up2(unsigned long long v) {
    unsigned int lo, hi;
    asm("mov.b64 {%0, %1}, %2;" : "=r"(lo), "=r"(hi) : "l"(v));
    return make_float2(__uint_as_float(lo), __uint_as_float(hi));
}

// ---------------- 4x4 stride-2 conv, FFMA2, 2x2 output tile, CO=16 -------------
// thread = (n, y-pair, x-pair): 2x2 output pixels, 16 output channels (blockIdx.y).
// 6x6 input patch per ci; each weight LDS.128 feeds 4 pixels (LDS:FFMA2 = 1:8).
template<int CIN, int CCHUNK, bool RELU, bool VEC2>
__global__ void __launch_bounds__(256, 2)
conv4x4s2_q(const float* __restrict__ in0, const float* __restrict__ in1, int N0,
            const float* __restrict__ w, const float* __restrict__ bias,
            float* __restrict__ out,
            int N, int Hin, int Win, int Hout, int Wout, int CO_TOTAL)
{
    constexpr int CO = 16;
    __shared__ __align__(16) float sw[CCHUNK * 16 * CO];
    const int tid = threadIdx.x;
    const int coBase = blockIdx.y * CO;
    const int XP = Wout >> 1, YP = Hout >> 1;
    const int total = N * YP * XP;
    const int pos = blockIdx.x * 256 + tid;
    const bool active = pos < total;
    const int p = active ? pos : 0;
    const int xp = p % XP;
    const int t1 = p / XP;
    const int yp = t1 % YP;
    const int n  = t1 / YP;

    const float* inb = (n < N0) ? in0 : in1;
    const int nn = (n < N0) ? n : n - N0;

    // acc[pix][j]: pix = oy*2+ox, j = co-pair
    unsigned long long acc[4][CO/2];
#pragma unroll
    for (int j = 0; j < CO/2; ++j) {
        unsigned long long b = pk2(__ldg(bias + coBase + 2*j), __ldg(bias + coBase + 2*j + 1));
        acc[0][j] = b; acc[1][j] = b; acc[2][j] = b; acc[3][j] = b;
    }

    const int y0 = yp * 4, x0 = xp * 4;

    for (int c0 = 0; c0 < CIN; c0 += CCHUNK) {
        __syncthreads();
        constexpr int NLD = CCHUNK * 16 * CO / 4;
        for (int i = tid; i < NLD; i += 256) {
            int co   = i % CO;
            int rest = i / CO;
            int cc   = rest % CCHUNK;
            int t4   = rest / CCHUNK;
            float4 wv = __ldg(reinterpret_cast<const float4*>(
                              w + (((coBase + co) * CIN + c0 + cc) * 16 + t4 * 4)));
            int base = (cc * 16 + t4 * 4) * CO + co;
            sw[base]        = wv.x;
            sw[base + CO]   = wv.y;
            sw[base + 2*CO] = wv.z;
            sw[base + 3*CO] = wv.w;
        }
        __syncthreads();

        for (int cc = 0; cc < CCHUNK; ++cc) {
            const float* ip = inb + ((nn * CIN + c0 + cc) * Hin + y0) * Win + x0;
            float patch[6][6];
            if (VEC2) {
#pragma unroll
                for (int r = 0; r < 6; ++r) {
#pragma unroll
                    for (int j = 0; j < 3; ++j) {
                        float2 v = __ldg(reinterpret_cast<const float2*>(ip + r * Win + 2*j));
                        patch[r][2*j]   = v.x;
                        patch[r][2*j+1] = v.y;
                    }
                }
            } else {
#pragma unroll
                for (int r = 0; r < 6; ++r)
#pragma unroll
                    for (int c = 0; c < 6; ++c)
                        patch[r][c] = __ldg(ip + r * Win + c);
            }
#pragma unroll
            for (int kh = 0; kh < 4; ++kh) {
#pragma unroll
                for (int kw = 0; kw < 4; ++kw) {
                    const unsigned long long x00 = pk_dup(patch[kh][kw]);
                    const unsigned long long x01 = pk_dup(patch[kh][kw + 2]);
                    const unsigned long long x10 = pk_dup(patch[kh + 2][kw]);
                    const unsigned long long x11 = pk_dup(patch[kh + 2][kw + 2]);
                    const ulonglong2* wr = reinterpret_cast<const ulonglong2*>(
                        &sw[(cc * 16 + kh * 4 + kw) * CO]);
#pragma unroll
                    for (int c4 = 0; c4 < CO/4; ++c4) {
                        ulonglong2 u = wr[c4];
                        fma2(acc[0][2*c4],   x00, u.x); fma2(acc[0][2*c4+1], x00, u.y);
                        fma2(acc[1][2*c4],   x01, u.x); fma2(acc[1][2*c4+1], x01, u.y);
                        fma2(acc[2][2*c4],   x10, u.x); fma2(acc[2][2*c4+1], x10, u.y);
                        fma2(acc[3][2*c4],   x11, u.x); fma2(acc[3][2*c4+1], x11, u.y);
                    }
                }
            }
        }
    }

    if (active) {
        const int hw = Hout * Wout;
        const int yy = yp * 2, xx = xp * 2;
        float* op = out + ((n * CO_TOTAL + coBase) * Hout + yy) * Wout + xx;
#pragma unroll
        for (int j = 0; j < CO/2; ++j) {
            float2 p00 = up2(acc[0][j]);  // (co 2j, 2j+1) @ (yy, xx)
            float2 p01 = up2(acc[1][j]);  // @ (yy, xx+1)
            float2 p10 = up2(acc[2][j]);  // @ (yy+1, xx)
            float2 p11 = up2(acc[3][j]);  // @ (yy+1, xx+1)
            if (RELU) {
                p00.x = fmaxf(p00.x, 0.f); p00.y = fmaxf(p00.y, 0.f);
                p01.x = fmaxf(p01.x, 0.f); p01.y = fmaxf(p01.y, 0.f);
                p10.x = fmaxf(p10.x, 0.f); p10.y = fmaxf(p10.y, 0.f);
                p11.x = fmaxf(p11.x, 0.f); p11.y = fmaxf(p11.y, 0.f);
            }
            float* o0 = op + (2*j) * hw;
            float* o1 = op + (2*j+1) * hw;
            *reinterpret_cast<float2*>(o0)        = make_float2(p00.x, p01.x);
            *reinterpret_cast<float2*>(o0 + Wout) = make_float2(p10.x, p11.x);
            *reinterpret_cast<float2*>(o1)        = make_float2(p00.y, p01.y);
            *reinterpret_cast<float2*>(o1 + Wout) = make_float2(p10.y, p11.y);
        }
    }
}

// ---------------- transposed conv, stride 2, VALID, parity-specialized -------------
template<int K, int CIN, int COUT, int CCHUNK, bool RELU, bool SIG>
__global__ void __launch_bounds__(256)
deconv_s2_kernel(const float* __restrict__ in, const float* __restrict__ w,
                 const float* __restrict__ bias, float* __restrict__ out,
                 int N, int Hin, int Win, int Hout, int Wout)
{
    constexpr int KK = K * K;
    constexpr int PAD = K - 1;
    __shared__ __align__(16) float sw[CCHUNK * KK * COUT];
    const int tid = threadIdx.x;
    const int total = N * Hout * Wout;
    const int pos = blockIdx.x * 256 + tid;
    const bool active = pos < total;
    const int p = active ? pos : 0;
    const int x = p % Wout;
    const int t1 = p / Wout;
    const int y = t1 % Hout;
    const int n = t1 / Hout;

    float acc[COUT];
#pragma unroll
    for (int co = 0; co < COUT; ++co) acc[co] = __ldg(bias + co);

    const int kh0 = (PAD + y) & 1;
    const int kw0 = (PAD + x) & 1;

    for (int c0 = 0; c0 < CIN; c0 += CCHUNK) {
        __syncthreads();
        for (int i = tid; i < CCHUNK * KK * COUT; i += 256) {
            int co   = i % COUT;
            int rest = i / COUT;
            int t    = rest % KK;
            int cc   = rest / KK;
            sw[(cc * KK + t) * COUT + co] = __ldg(w + (co * CIN + c0 + cc) * KK + t);
        }
        __syncthreads();

        for (int cc = 0; cc < CCHUNK; ++cc) {
            const float* ip = in + (n * CIN + c0 + cc) * Hin * Win;
            for (int kh = kh0; kh < K; kh += 2) {
                const int iy = (y + kh - PAD) >> 1;
                if (iy < 0 || iy >= Hin) continue;
                for (int kw = kw0; kw < K; kw += 2) {
                    const int ix = (x + kw - PAD) >> 1;
                    if (ix < 0 || ix >= Win) continue;
                    const float xv = __ldg(ip + iy * Win + ix);
                    const float* wr = &sw[(cc * KK + kh * K + kw) * COUT];
                    if constexpr ((COUT % 4) == 0) {
                        const float4* wr4 = reinterpret_cast<const float4*>(wr);
#pragma unroll
                        for (int c4 = 0; c4 < COUT / 4; ++c4) {
                            float4 wv = wr4[c4];
                            acc[c4*4+0] = fmaf(xv, wv.x, acc[c4*4+0]);
                            acc[c4*4+1] = fmaf(xv, wv.y, acc[c4*4+1]);
                            acc[c4*4+2] = fmaf(xv, wv.z, acc[c4*4+2]);
                            acc[c4*4+3] = fmaf(xv, wv.w, acc[c4*4+3]);
                        }
                    } else {
#pragma unroll
                        for (int co = 0; co < COUT; ++co)
                            acc[co] = fmaf(xv, wr[co], acc[co]);
                    }
                }
            }
        }
    }

    if (active) {
        float* op = out + (n * COUT * Hout + y) * Wout + x;
        const int hw = Hout * Wout;
#pragma unroll
        for (int co = 0; co < COUT; ++co) {
            float v = acc[co];
            if (RELU) v = fmaxf(v, 0.0f);
            if (SIG)  v = 1.0f / (1.0f + __expf(-v));
            op[co * hw] = v;
        }
    }
}

// ---------------- 1x1 conv ----------------
template<int CIN, int COUT, bool RELU>
__global__ void __launch_bounds__(256)
conv1x1_kernel(const float* __restrict__ in, const float* __restrict__ w,
               const float* __restrict__ bias, float* __restrict__ out,
               int N, int HW)
{
    __shared__ __align__(16) float sw[CIN * COUT];
    const int tid = threadIdx.x;
    for (int i = tid; i < CIN * COUT; i += 256) {
        int co = i % COUT;
        int ci = i / COUT;
        sw[i] = __ldg(w + co * CIN + ci);
    }
    __syncthreads();
    const int pos = blockIdx.x * 256 + tid;
    if (pos >= N * HW) return;
    const int sp = pos % HW;
    const int n  = pos / HW;

    float acc[COUT];
#pragma unroll
    for (int co = 0; co < COUT; ++co) acc[co] = __ldg(bias + co);

    for (int ci = 0; ci < CIN; ++ci) {
        const float xv = __ldg(in + (n * CIN + ci) * HW + sp);
        const float4* wr = reinterpret_cast<const float4*>(&sw[ci * COUT]);
#pragma unroll
        for (int c4 = 0; c4 < COUT / 4; ++c4) {
            float4 wv = wr[c4];
            acc[c4*4+0] = fmaf(xv, wv.x, acc[c4*4+0]);
            acc[c4*4+1] = fmaf(xv, wv.y, acc[c4*4+1]);
            acc[c4*4+2] = fmaf(xv, wv.z, acc[c4*4+2]);
            acc[c4*4+3] = fmaf(xv, wv.w, acc[c4*4+3]);
        }
    }
    float* op = out + n * COUT * HW + sp;
#pragma unroll
    for (int co = 0; co < COUT; ++co) {
        float v = acc[co];
        if (RELU) v = fmaxf(v, 0.0f);
        op[co * HW] = v;
    }
}

// ---------------- fused VAE heads ----------------
__global__ void __launch_bounds__(256)
vae_heads_kernel(const float* __restrict__ h,
                 const float* __restrict__ mw, const float* __restrict__ mb,
                 const float* __restrict__ lw, const float* __restrict__ lb,
                 const float* __restrict__ eps,
                 float* __restrict__ out_mu, float* __restrict__ out_lv,
                 float* __restrict__ z)
{
    constexpr int HW = 196, N = 64;
    __shared__ __align__(16) float smw[64 * 32];
    __shared__ __align__(16) float slw[64 * 32];
    const int tid = threadIdx.x;
    for (int i = tid; i < 64 * 32; i += 256) {
        int co = i % 32;
        int ci = i / 32;
        smw[i] = __ldg(mw + co * 64 + ci);
        slw[i] = __ldg(lw + co * 64 + ci);
    }
    __syncthreads();
    const int pos = blockIdx.x * 256 + tid;
    if (pos >= N * HW) return;
    const int sp = pos % HW;
    const int n  = pos / HW;

    float am[32], al[32];
#pragma unroll
    for (int co = 0; co < 32; ++co) { am[co] = __ldg(mb + co); al[co] = __ldg(lb + co); }

    for (int ci = 0; ci < 64; ++ci) {
        const float xv = __ldg(h + (n * 64 + ci) * HW + sp);
        const float4* wm = reinterpret_cast<const float4*>(&smw[ci * 32]);
        const float4* wl = reinterpret_cast<const float4*>(&slw[ci * 32]);
#pragma unroll
        for (int c4 = 0; c4 < 8; ++c4) {
            float4 a = wm[c4], b = wl[c4];
            am[c4*4+0] = fmaf(xv, a.x, am[c4*4+0]);
            am[c4*4+1] = fmaf(xv, a.y, am[c4*4+1]);
            am[c4*4+2] = fmaf(xv, a.z, am[c4*4+2]);
            am[c4*4+3] = fmaf(xv, a.w, am[c4*4+3]);
            al[c4*4+0] = fmaf(xv, b.x, al[c4*4+0]);
            al[c4*4+1] = fmaf(xv, b.y, al[c4*4+1]);
            al[c4*4+2] = fmaf(xv, b.z, al[c4*4+2]);
            al[c4*4+3] = fmaf(xv, b.w, al[c4*4+3]);
        }
    }
#pragma unroll
    for (int co = 0; co < 32; ++co) {
        const int idx = (n * 32 + co) * HW + sp;
        const float mu = am[co], lv = al[co];
        out_mu[idx] = mu;
        out_lv[idx] = lv;
        z[idx] = mu + __ldg(eps + idx) * __expf(0.5f * lv);
    }
}

// ---------------- xcorr, register-blocked sliding window ----------------
__global__ void __launch_bounds__(128)
xcorr_kernel(const float* __restrict__ pnf, const float* __restrict__ af,
             float* __restrict__ out)
{
    __shared__ float sa[32 * 196];
    __shared__ float sacc[4 * 289];
    const int tid = threadIdx.x;
    const int cg  = tid >> 5;
    const int y   = tid & 31;
    const int n   = blockIdx.x;
    const int br  = blockIdx.y;
    const bool act = (y < 17);

    float acc[17];
#pragma unroll
    for (int x = 0; x < 17; ++x) acc[x] = 0.f;

    for (int c0 = 0; c0 < 64; c0 += 32) {
        __syncthreads();
        for (int i = tid; i < 32 * 196; i += 128) sa[i] = __ldg(af + c0 * 196 + i);
        __syncthreads();
        if (act) {
            for (int c = 0; c < 8; ++c) {
                const int ci = c0 + cg * 8 + c;
                const float* ip = pnf + ((br * 64 + n) * 64 + ci) * 900;
                const float* ap = sa + (cg * 8 + c) * 196;
                for (int dy = 0; dy < 14; ++dy) {
                    float r[30];
                    const float2* rp = reinterpret_cast<const float2*>(ip + (y + dy) * 30);
#pragma unroll
                    for (int j = 0; j < 15; ++j) {
                        float2 v = __ldg(rp + j);
                        r[2*j] = v.x; r[2*j+1] = v.y;
                    }
                    const float* arow = ap + dy * 14;
#pragma unroll
                    for (int dx = 0; dx < 14; ++dx) {
                        const float a = arow[dx];
#pragma unroll
                        for (int x = 0; x < 17; ++x)
                            acc[x] = fmaf(a, r[x + dx], acc[x]);
                    }
                }
            }
        }
    }

    if (act) {
#pragma unroll
        for (int x = 0; x < 17; ++x) sacc[cg * 289 + y * 17 + x] = acc[x];
    }
    __syncthreads();
    for (int i = tid; i < 289; i += 128) {
        float s = sacc[i] + sacc[289 + i] + sacc[2*289 + i] + sacc[3*289 + i];
        out[(br ? OFF_CXN : OFF_CXP) + n * 289 + i] = s;
    }
}

// ---------------- anchor broadcast ----------------
__global__ void bcast_kernel(const float* __restrict__ a, float* __restrict__ out)
{
    const int i = blockIdx.x * blockDim.x + threadIdx.x;
    if (i < ANCHOR_ELEMS) out[blockIdx.y * ANCHOR_ELEMS + i] = __ldg(a + i);
}

// ---------------- launcher ----------------
extern "C" void kernel_launch(void* const* d_in, const int* in_sizes, int n_in,
                              void* d_out, int out_size)
{
    const float* pos         = (const float*)d_in[0];
    const float* neg         = (const float*)d_in[1];
    const float* pos_crop    = (const float*)d_in[2];
    const float* eps         = (const float*)d_in[3];
    const float* anchor_crop = (const float*)d_in[4];
    const float* ew1 = (const float*)d_in[5],  *eb1 = (const float*)d_in[6];
    const float* ew2 = (const float*)d_in[7],  *eb2 = (const float*)d_in[8];
    const float* ew3 = (const float*)d_in[9],  *eb3 = (const float*)d_in[10];
    const float* mw  = (const float*)d_in[11], *mb  = (const float*)d_in[12];
    const float* lw  = (const float*)d_in[13], *lb  = (const float*)d_in[14];
    const float* dw0 = (const float*)d_in[15], *db0 = (const float*)d_in[16];
    const float* dw1 = (const float*)d_in[17], *db1 = (const float*)d_in[18];
    const float* dw2 = (const float*)d_in[19], *db2 = (const float*)d_in[20];
    const float* dw3 = (const float*)d_in[21], *db3 = (const float*)d_in[22];
    float* out = (float*)d_out;

    float *b1, *b2, *pnf, *h, *z, *d0, *d1, *d2;
    cudaGetSymbolAddress((void**)&b1,  g_buf1);
    cudaGetSymbolAddress((void**)&b2,  g_buf2);
    cudaGetSymbolAddress((void**)&pnf, g_pnf);
    cudaGetSymbolAddress((void**)&h,   g_h);
    cudaGetSymbolAddress((void**)&z,   g_z);
    cudaGetSymbolAddress((void**)&d0,  g_d0);
    cudaGetSymbolAddress((void**)&d1,  g_d1);
    cudaGetSymbolAddress((void**)&d2,  g_d2);
    const float* af = h + 64*64*196;   // anchor features at batch slot 64

    // anchor output = broadcast
    bcast_kernel<<<dim3(div_up(ANCHOR_ELEMS, 256), 64), 256>>>(anchor_crop, out + OFF_ANCHOR);

    // pos+neg encoder, fused N=128: 255 -> 126 -> 62 -> 30
    conv4x4s2_q<3, 3, true, false><<<dim3(div_up(128*63*63, 256), 2), 256>>>(
        pos, neg, 64, ew1, eb1, b1, 128, 255, 255, 126, 126, 32);
    conv4x4s2_q<32, 32, true, true><<<dim3(div_up(128*31*31, 256), 4), 256>>>(
        b1, b1, 128, ew2, eb2, b2, 128, 126, 126, 62, 62, 64);
    conv4x4s2_q<64, 32, true, true><<<dim3(div_up(128*15*15, 256), 4), 256>>>(
        b2, b2, 128, ew3, eb3, pnf, 128, 62, 62, 30, 30, 64);

    // crop+anchor encoder, fused N=65: 127 -> 62 -> 30 -> 14
    conv4x4s2_q<3, 3, true, false><<<dim3(div_up(65*31*31, 256), 2), 256>>>(
        pos_crop, anchor_crop, 64, ew1, eb1, b1, 65, 127, 127, 62, 62, 32);
    conv4x4s2_q<32, 32, true, true><<<dim3(div_up(65*15*15, 256), 4), 256>>>(
        b1, b1, 65, ew2, eb2, b2, 65, 62, 62, 30, 30, 64);
    conv4x4s2_q<64, 32, true, true><<<dim3(div_up(65*7*7, 256), 4), 256>>>(
        b2, b2, 65, ew3, eb3, h, 65, 30, 30, 14, 14, 64);

    // VAE heads + reparameterization
    vae_heads_kernel<<<div_up(64*196, 256), 256>>>(h, mw, mb, lw, lb, eps,
                                                   out + OFF_MU, out + OFF_LV, z);

    // decoder
    conv1x1_kernel<32, 64, true><<<div_up(64*196, 256), 256>>>(z, dw0, db0, d0, 64, 196);
    deconv_s2_kernel<4, 64, 32, 8, true, false><<<div_up(64*30*30, 256), 256>>>(d0, dw1, db1, d1, 64, 14, 14, 30, 30);
    deconv_s2_kernel<4, 32, 16, 8, true, false><<<div_up(64*62*62, 256), 256>>>(d1, dw2, db2, d2, 64, 30, 30, 62, 62);
    deconv_s2_kernel<5, 16, 3, 16, false, true><<<div_up(64*127*127, 256), 256>>>(d2, dw3, db3, out + OFF_RECON, 64, 62, 62, 127, 127);

    // cross-correlations
    xcorr_kernel<<<dim3(64, 2), 128>>>(pnf, af, out);
}

// round 6
// speedup vs baseline: 1.0040x; 1.0040x over previous
#include <cuda_runtime.h>
#include <math.h>

// ---------------- output layout (concatenated tuple, fp32) ----------------
#define ANCHOR_ELEMS (3*127*127)
#define N_ANCHOR     (64*ANCHOR_ELEMS)
#define N_CX         (64*17*17)
#define N_MU         (64*32*14*14)
#define OFF_ANCHOR   0
#define OFF_CXP      (OFF_ANCHOR + N_ANCHOR)
#define OFF_CXN      (OFF_CXP + N_CX)
#define OFF_RECON    (OFF_CXN + N_CX)
#define OFF_MU       (OFF_RECON + N_ANCHOR)
#define OFF_LV       (OFF_MU + N_MU)

// ---------------- scratch ----------------
__device__ float g_buf1[128*32*126*126];  // conv1 out
__device__ float g_buf2[128*64*62*62];    // conv2 out
__device__ float g_pnf [128*64*30*30];    // conv3 out (pos+neg)
__device__ float g_h   [65*64*14*14];     // crop conv3 out (n=64 is anchor)
__device__ float g_z   [64*32*14*14];
__device__ float g_d0  [64*64*14*14];
__device__ float g_d1  [64*32*30*30];
__device__ float g_d2  [64*16*62*62];

static inline int div_up(int a, int b) { return (a + b - 1) / b; }

// ---------------- f32x2 packed-FMA helpers ----------------
__device__ __forceinline__ unsigned long long pk_dup(float v) {
    unsigned long long r; unsigned int u = __float_as_uint(v);
    asm("mov.b64 %0, {%1, %1};" : "=l"(r) : "r"(u));
    return r;
}
__device__ __forceinline__ unsigned long long pk2(float a, float b) {
    unsigned long long r;
    asm("mov.b64 %0, {%1, %2};" : "=l"(r) : "r"(__float_as_uint(a)), "r"(__float_as_uint(b)));
    return r;
}
__device__ __forceinline__ void fma2(unsigned long long& acc, unsigned long long a, unsigned long long b) {
    asm("fma.rn.f32x2 %0, %1, %2, %0;" : "+l"(acc) : "l"(a), "l"(b));
}
__device__ __forceinline__ float2 up2(unsigned long long v) {
    unsigned int lo, hi;
    asm("mov.b64 {%0, %1}, %2;" : "=r"(lo), "=r"(hi) : "l"(v));
    return make_float2(__uint_as_float(lo), __uint_as_float(hi));
}

// ---------------- 4x4 stride-2 conv, FFMA2, 2x2 output tile, CO=16 -------------
// thread = (n, y-pair, x-pair): 2x2 output pixels, 16 output channels (blockIdx.y).
// 6x6 input patch per ci; each weight LDS.128 feeds 4 pixels (LDS:FFMA2 = 1:8).
template<int CIN, int CCHUNK, bool RELU, bool VEC2>
__global__ void __launch_bounds__(256, 2)
conv4x4s2_q(const float* __restrict__ in0, const float* __restrict__ in1, int N0,
            const float* __restrict__ w, const float* __restrict__ bias,
            float* __restrict__ out,
            int N, int Hin, int Win, int Hout, int Wout, int CO_TOTAL)
{
    constexpr int CO = 16;
    __shared__ __align__(16) float sw[CCHUNK * 16 * CO];
    const int tid = threadIdx.x;
    const int coBase = blockIdx.y * CO;
    const int XP = Wout >> 1, YP = Hout >> 1;
    const int total = N * YP * XP;
    const int pos = blockIdx.x * 256 + tid;
    const bool active = pos < total;
    const int p = active ? pos : 0;
    const int xp = p % XP;
    const int t1 = p / XP;
    const int yp = t1 % YP;
    const int n  = t1 / YP;

    const float* inb = (n < N0) ? in0 : in1;
    const int nn = (n < N0) ? n : n - N0;

    // acc[pix][j]: pix = oy*2+ox, j = co-pair
    unsigned long long acc[4][CO/2];
#pragma unroll
    for (int j = 0; j < CO/2; ++j) {
        unsigned long long b = pk2(__ldg(bias + coBase + 2*j), __ldg(bias + coBase + 2*j + 1));
        acc[0][j] = b; acc[1][j] = b; acc[2][j] = b; acc[3][j] = b;
    }

    const int y0 = yp * 4, x0 = xp * 4;

    for (int c0 = 0; c0 < CIN; c0 += CCHUNK) {
        __syncthreads();
        constexpr int NLD = CCHUNK * 16 * CO / 4;
        for (int i = tid; i < NLD; i += 256) {
            int co   = i % CO;
            int rest = i / CO;
            int cc   = rest % CCHUNK;
            int t4   = rest / CCHUNK;
            float4 wv = __ldg(reinterpret_cast<const float4*>(
                              w + (((coBase + co) * CIN + c0 + cc) * 16 + t4 * 4)));
            int base = (cc * 16 + t4 * 4) * CO + co;
            sw[base]        = wv.x;
            sw[base + CO]   = wv.y;
            sw[base + 2*CO] = wv.z;
            sw[base + 3*CO] = wv.w;
        }
        __syncthreads();

        for (int cc = 0; cc < CCHUNK; ++cc) {
            const float* ip = inb + ((nn * CIN + c0 + cc) * Hin + y0) * Win + x0;
            float patch[6][6];
            if (VEC2) {
#pragma unroll
                for (int r = 0; r < 6; ++r) {
#pragma unroll
                    for (int j = 0; j < 3; ++j) {
                        float2 v = __ldg(reinterpret_cast<const float2*>(ip + r * Win + 2*j));
                        patch[r][2*j]   = v.x;
                        patch[r][2*j+1] = v.y;
                    }
                }
            } else {
#pragma unroll
                for (int r = 0; r < 6; ++r)
#pragma unroll
                    for (int c = 0; c < 6; ++c)
                        patch[r][c] = __ldg(ip + r * Win + c);
            }
#pragma unroll
            for (int kh = 0; kh < 4; ++kh) {
#pragma unroll
                for (int kw = 0; kw < 4; ++kw) {
                    const unsigned long long x00 = pk_dup(patch[kh][kw]);
                    const unsigned long long x01 = pk_dup(patch[kh][kw + 2]);
                    const unsigned long long x10 = pk_dup(patch[kh + 2][kw]);
                    const unsigned long long x11 = pk_dup(patch[kh + 2][kw + 2]);
                    const ulonglong2* wr = reinterpret_cast<const ulonglong2*>(
                        &sw[(cc * 16 + kh * 4 + kw) * CO]);
#pragma unroll
                    for (int c4 = 0; c4 < CO/4; ++c4) {
                        ulonglong2 u = wr[c4];
                        fma2(acc[0][2*c4],   x00, u.x); fma2(acc[0][2*c4+1], x00, u.y);
                        fma2(acc[1][2*c4],   x01, u.x); fma2(acc[1][2*c4+1], x01, u.y);
                        fma2(acc[2][2*c4],   x10, u.x); fma2(acc[2][2*c4+1], x10, u.y);
                        fma2(acc[3][2*c4],   x11, u.x); fma2(acc[3][2*c4+1], x11, u.y);
                    }
                }
            }
        }
    }

    if (active) {
        const int hw = Hout * Wout;
        const int yy = yp * 2, xx = xp * 2;
        float* op = out + ((n * CO_TOTAL + coBase) * Hout + yy) * Wout + xx;
#pragma unroll
        for (int j = 0; j < CO/2; ++j) {
            float2 p00 = up2(acc[0][j]);  // (co 2j, 2j+1) @ (yy, xx)
            float2 p01 = up2(acc[1][j]);  // @ (yy, xx+1)
            float2 p10 = up2(acc[2][j]);  // @ (yy+1, xx)
            float2 p11 = up2(acc[3][j]);  // @ (yy+1, xx+1)
            if (RELU) {
                p00.x = fmaxf(p00.x, 0.f); p00.y = fmaxf(p00.y, 0.f);
                p01.x = fmaxf(p01.x, 0.f); p01.y = fmaxf(p01.y, 0.f);
                p10.x = fmaxf(p10.x, 0.f); p10.y = fmaxf(p10.y, 0.f);
                p11.x = fmaxf(p11.x, 0.f); p11.y = fmaxf(p11.y, 0.f);
            }
            float* o0 = op + (2*j) * hw;
            float* o1 = op + (2*j+1) * hw;
            *reinterpret_cast<float2*>(o0)        = make_float2(p00.x, p01.x);
            *reinterpret_cast<float2*>(o0 + Wout) = make_float2(p10.x, p11.x);
            *reinterpret_cast<float2*>(o1)        = make_float2(p00.y, p01.y);
            *reinterpret_cast<float2*>(o1 + Wout) = make_float2(p10.y, p11.y);
        }
    }
}

// ---------------- transposed conv, stride 2, VALID, parity-specialized -------------
template<int K, int CIN, int COUT, int CCHUNK, bool RELU, bool SIG>
__global__ void __launch_bounds__(256)
deconv_s2_kernel(const float* __restrict__ in, const float* __restrict__ w,
                 const float* __restrict__ bias, float* __restrict__ out,
                 int N, int Hin, int Win, int Hout, int Wout)
{
    constexpr int KK = K * K;
    constexpr int PAD = K - 1;
    __shared__ __align__(16) float sw[CCHUNK * KK * COUT];
    const int tid = threadIdx.x;
    const int total = N * Hout * Wout;
    const int pos = blockIdx.x * 256 + tid;
    const bool active = pos < total;
    const int p = active ? pos : 0;
    const int x = p % Wout;
    const int t1 = p / Wout;
    const int y = t1 % Hout;
    const int n = t1 / Hout;

    float acc[COUT];
#pragma unroll
    for (int co = 0; co < COUT; ++co) acc[co] = __ldg(bias + co);

    const int kh0 = (PAD + y) & 1;
    const int kw0 = (PAD + x) & 1;

    for (int c0 = 0; c0 < CIN; c0 += CCHUNK) {
        __syncthreads();
        for (int i = tid; i < CCHUNK * KK * COUT; i += 256) {
            int co   = i % COUT;
            int rest = i / COUT;
            int t    = rest % KK;
            int cc   = rest / KK;
            sw[(cc * KK + t) * COUT + co] = __ldg(w + (co * CIN + c0 + cc) * KK + t);
        }
        __syncthreads();

        for (int cc = 0; cc < CCHUNK; ++cc) {
            const float* ip = in + (n * CIN + c0 + cc) * Hin * Win;
            for (int kh = kh0; kh < K; kh += 2) {
                const int iy = (y + kh - PAD) >> 1;
                if (iy < 0 || iy >= Hin) continue;
                for (int kw = kw0; kw < K; kw += 2) {
                    const int ix = (x + kw - PAD) >> 1;
                    if (ix < 0 || ix >= Win) continue;
                    const float xv = __ldg(ip + iy * Win + ix);
                    const float* wr = &sw[(cc * KK + kh * K + kw) * COUT];
                    if constexpr ((COUT % 4) == 0) {
                        const float4* wr4 = reinterpret_cast<const float4*>(wr);
#pragma unroll
                        for (int c4 = 0; c4 < COUT / 4; ++c4) {
                            float4 wv = wr4[c4];
                            acc[c4*4+0] = fmaf(xv, wv.x, acc[c4*4+0]);
                            acc[c4*4+1] = fmaf(xv, wv.y, acc[c4*4+1]);
                            acc[c4*4+2] = fmaf(xv, wv.z, acc[c4*4+2]);
                            acc[c4*4+3] = fmaf(xv, wv.w, acc[c4*4+3]);
                        }
                    } else {
#pragma unroll
                        for (int co = 0; co < COUT; ++co)
                            acc[co] = fmaf(xv, wr[co], acc[co]);
                    }
                }
            }
        }
    }

    if (active) {
        float* op = out + (n * COUT * Hout + y) * Wout + x;
        const int hw = Hout * Wout;
#pragma unroll
        for (int co = 0; co < COUT; ++co) {
            float v = acc[co];
            if (RELU) v = fmaxf(v, 0.0f);
            if (SIG)  v = 1.0f / (1.0f + __expf(-v));
            op[co * hw] = v;
        }
    }
}

// ---------------- 1x1 conv ----------------
template<int CIN, int COUT, bool RELU>
__global__ void __launch_bounds__(256)
conv1x1_kernel(const float* __restrict__ in, const float* __restrict__ w,
               const float* __restrict__ bias, float* __restrict__ out,
               int N, int HW)
{
    __shared__ __align__(16) float sw[CIN * COUT];
    const int tid = threadIdx.x;
    for (int i = tid; i < CIN * COUT; i += 256) {
        int co = i % COUT;
        int ci = i / COUT;
        sw[i] = __ldg(w + co * CIN + ci);
    }
    __syncthreads();
    const int pos = blockIdx.x * 256 + tid;
    if (pos >= N * HW) return;
    const int sp = pos % HW;
    const int n  = pos / HW;

    float acc[COUT];
#pragma unroll
    for (int co = 0; co < COUT; ++co) acc[co] = __ldg(bias + co);

    for (int ci = 0; ci < CIN; ++ci) {
        const float xv = __ldg(in + (n * CIN + ci) * HW + sp);
        const float4* wr = reinterpret_cast<const float4*>(&sw[ci * COUT]);
#pragma unroll
        for (int c4 = 0; c4 < COUT / 4; ++c4) {
            float4 wv = wr[c4];
            acc[c4*4+0] = fmaf(xv, wv.x, acc[c4*4+0]);
            acc[c4*4+1] = fmaf(xv, wv.y, acc[c4*4+1]);
            acc[c4*4+2] = fmaf(xv, wv.z, acc[c4*4+2]);
            acc[c4*4+3] = fmaf(xv, wv.w, acc[c4*4+3]);
        }
    }
    float* op = out + n * COUT * HW + sp;
#pragma unroll
    for (int co = 0; co < COUT; ++co) {
        float v = acc[co];
        if (RELU) v = fmaxf(v, 0.0f);
        op[co * HW] = v;
    }
}

// ---------------- fused VAE heads ----------------
__global__ void __launch_bounds__(256)
vae_heads_kernel(const float* __restrict__ h,
                 const float* __restrict__ mw, const float* __restrict__ mb,
                 const float* __restrict__ lw, const float* __restrict__ lb,
                 const float* __restrict__ eps,
                 float* __restrict__ out_mu, float* __restrict__ out_lv,
                 float* __restrict__ z)
{
    constexpr int HW = 196, N = 64;
    __shared__ __align__(16) float smw[64 * 32];
    __shared__ __align__(16) float slw[64 * 32];
    const int tid = threadIdx.x;
    for (int i = tid; i < 64 * 32; i += 256) {
        int co = i % 32;
        int ci = i / 32;
        smw[i] = __ldg(mw + co * 64 + ci);
        slw[i] = __ldg(lw + co * 64 + ci);
    }
    __syncthreads();
    const int pos = blockIdx.x * 256 + tid;
    if (pos >= N * HW) return;
    const int sp = pos % HW;
    const int n  = pos / HW;

    float am[32], al[32];
#pragma unroll
    for (int co = 0; co < 32; ++co) { am[co] = __ldg(mb + co); al[co] = __ldg(lb + co); }

    for (int ci = 0; ci < 64; ++ci) {
        const float xv = __ldg(h + (n * 64 + ci) * HW + sp);
        const float4* wm = reinterpret_cast<const float4*>(&smw[ci * 32]);
        const float4* wl = reinterpret_cast<const float4*>(&slw[ci * 32]);
#pragma unroll
        for (int c4 = 0; c4 < 8; ++c4) {
            float4 a = wm[c4], b = wl[c4];
            am[c4*4+0] = fmaf(xv, a.x, am[c4*4+0]);
            am[c4*4+1] = fmaf(xv, a.y, am[c4*4+1]);
            am[c4*4+2] = fmaf(xv, a.z, am[c4*4+2]);
            am[c4*4+3] = fmaf(xv, a.w, am[c4*4+3]);
            al[c4*4+0] = fmaf(xv, b.x, al[c4*4+0]);
            al[c4*4+1] = fmaf(xv, b.y, al[c4*4+1]);
            al[c4*4+2] = fmaf(xv, b.z, al[c4*4+2]);
            al[c4*4+3] = fmaf(xv, b.w, al[c4*4+3]);
        }
    }
#pragma unroll
    for (int co = 0; co < 32; ++co) {
        const int idx = (n * 32 + co) * HW + sp;
        const float mu = am[co], lv = al[co];
        out_mu[idx] = mu;
        out_lv[idx] = lv;
        z[idx] = mu + __ldg(eps + idx) * __expf(0.5f * lv);
    }
}

// ---------------- xcorr, register-blocked sliding window ----------------
__global__ void __launch_bounds__(128)
xcorr_kernel(const float* __restrict__ pnf, const float* __restrict__ af,
             float* __restrict__ out)
{
    __shared__ float sa[32 * 196];
    __shared__ float sacc[4 * 289];
    const int tid = threadIdx.x;
    const int cg  = tid >> 5;
    const int y   = tid & 31;
    const int n   = blockIdx.x;
    const int br  = blockIdx.y;
    const bool act = (y < 17);

    float acc[17];
#pragma unroll
    for (int x = 0; x < 17; ++x) acc[x] = 0.f;

    for (int c0 = 0; c0 < 64; c0 += 32) {
        __syncthreads();
        for (int i = tid; i < 32 * 196; i += 128) sa[i] = __ldg(af + c0 * 196 + i);
        __syncthreads();
        if (act) {
            for (int c = 0; c < 8; ++c) {
                const int ci = c0 + cg * 8 + c;
                const float* ip = pnf + ((br * 64 + n) * 64 + ci) * 900;
                const float* ap = sa + (cg * 8 + c) * 196;
                for (int dy = 0; dy < 14; ++dy) {
                    float r[30];
                    const float2* rp = reinterpret_cast<const float2*>(ip + (y + dy) * 30);
#pragma unroll
                    for (int j = 0; j < 15; ++j) {
                        float2 v = __ldg(rp + j);
                        r[2*j] = v.x; r[2*j+1] = v.y;
                    }
                    const float* arow = ap + dy * 14;
#pragma unroll
                    for (int dx = 0; dx < 14; ++dx) {
                        const float a = arow[dx];
#pragma unroll
                        for (int x = 0; x < 17; ++x)
                            acc[x] = fmaf(a, r[x + dx], acc[x]);
                    }
                }
            }
        }
    }

    if (act) {
#pragma unroll
        for (int x = 0; x < 17; ++x) sacc[cg * 289 + y * 17 + x] = acc[x];
    }
    __syncthreads();
    for (int i = tid; i < 289; i += 128) {
        float s = sacc[i] + sacc[289 + i] + sacc[2*289 + i] + sacc[3*289 + i];
        out[(br ? OFF_CXN : OFF_CXP) + n * 289 + i] = s;
    }
}

// ---------------- anchor broadcast ----------------
__global__ void bcast_kernel(const float* __restrict__ a, float* __restrict__ out)
{
    const int i = blockIdx.x * blockDim.x + threadIdx.x;
    if (i < ANCHOR_ELEMS) out[blockIdx.y * ANCHOR_ELEMS + i] = __ldg(a + i);
}

// ---------------- launcher ----------------
extern "C" void kernel_launch(void* const* d_in, const int* in_sizes, int n_in,
                              void* d_out, int out_size)
{
    const float* pos         = (const float*)d_in[0];
    const float* neg         = (const float*)d_in[1];
    const float* pos_crop    = (const float*)d_in[2];
    const float* eps         = (const float*)d_in[3];
    const float* anchor_crop = (const float*)d_in[4];
    const float* ew1 = (const float*)d_in[5],  *eb1 = (const float*)d_in[6];
    const float* ew2 = (const float*)d_in[7],  *eb2 = (const float*)d_in[8];
    const float* ew3 = (const float*)d_in[9],  *eb3 = (const float*)d_in[10];
    const float* mw  = (const float*)d_in[11], *mb  = (const float*)d_in[12];
    const float* lw  = (const float*)d_in[13], *lb  = (const float*)d_in[14];
    const float* dw0 = (const float*)d_in[15], *db0 = (const float*)d_in[16];
    const float* dw1 = (const float*)d_in[17], *db1 = (const float*)d_in[18];
    const float* dw2 = (const float*)d_in[19], *db2 = (const float*)d_in[20];
    const float* dw3 = (const float*)d_in[21], *db3 = (const float*)d_in[22];
    float* out = (float*)d_out;

    float *b1, *b2, *pnf, *h, *z, *d0, *d1, *d2;
    cudaGetSymbolAddress((void**)&b1,  g_buf1);
    cudaGetSymbolAddress((void**)&b2,  g_buf2);
    cudaGetSymbolAddress((void**)&pnf, g_pnf);
    cudaGetSymbolAddress((void**)&h,   g_h);
    cudaGetSymbolAddress((void**)&z,   g_z);
    cudaGetSymbolAddress((void**)&d0,  g_d0);
    cudaGetSymbolAddress((void**)&d1,  g_d1);
    cudaGetSymbolAddress((void**)&d2,  g_d2);
    const float* af = h + 64*64*196;   // anchor features at batch slot 64

    // anchor output = broadcast
    bcast_kernel<<<dim3(div_up(ANCHOR_ELEMS, 256), 64), 256>>>(anchor_crop, out + OFF_ANCHOR);

    // pos+neg encoder, fused N=128: 255 -> 126 -> 62 -> 30
    conv4x4s2_q<3, 3, true, false><<<dim3(div_up(128*63*63, 256), 2), 256>>>(
        pos, neg, 64, ew1, eb1, b1, 128, 255, 255, 126, 126, 32);
    conv4x4s2_q<32, 32, true, true><<<dim3(div_up(128*31*31, 256), 4), 256>>>(
        b1, b1, 128, ew2, eb2, b2, 128, 126, 126, 62, 62, 64);
    conv4x4s2_q<64, 32, true, true><<<dim3(div_up(128*15*15, 256), 4), 256>>>(
        b2, b2, 128, ew3, eb3, pnf, 128, 62, 62, 30, 30, 64);

    // crop+anchor encoder, fused N=65: 127 -> 62 -> 30 -> 14
    conv4x4s2_q<3, 3, true, false><<<dim3(div_up(65*31*31, 256), 2), 256>>>(
        pos_crop, anchor_crop, 64, ew1, eb1, b1, 65, 127, 127, 62, 62, 32);
    conv4x4s2_q<32, 32, true, true><<<dim3(div_up(65*15*15, 256), 4), 256>>>(
        b1, b1, 65, ew2, eb2, b2, 65, 62, 62, 30, 30, 64);
    conv4x4s2_q<64, 32, true, true><<<dim3(div_up(65*7*7, 256), 4), 256>>>(
        b2, b2, 65, ew3, eb3, h, 65, 30, 30, 14, 14, 64);

    // VAE heads + reparameterization
    vae_heads_kernel<<<div_up(64*196, 256), 256>>>(h, mw, mb, lw, lb, eps,
                                                   out + OFF_MU, out + OFF_LV, z);

    // decoder
    conv1x1_kernel<32, 64, true><<<div_up(64*196, 256), 256>>>(z, dw0, db0, d0, 64, 196);
    deconv_s2_kernel<4, 64, 32, 8, true, false><<<div_up(64*30*30, 256), 256>>>(d0, dw1, db1, d1, 64, 14, 14, 30, 30);
    deconv_s2_kernel<4, 32, 16, 8, true, false><<<div_up(64*62*62, 256), 256>>>(d1, dw2, db2, d2, 64, 30, 30, 62, 62);
    deconv_s2_kernel<5, 16, 3, 16, false, true><<<div_up(64*127*127, 256), 256>>>(d2, dw3, db3, out + OFF_RECON, 64, 62, 62, 127, 127);

    // cross-correlations
    xcorr_kernel<<<dim3(64, 2), 128>>>(pnf, af, out);
}